// round 1
// baseline (speedup 1.0000x reference)
#include <cuda_runtime.h>
#include <math.h>

#define NN 10000
#define TT 128
#define HH 128
#define EE 320000

// ---------------- device scratch (no allocations allowed) ----------------
__device__ __align__(16) float g_h1[NN * HH];
__device__ __align__(16) float g_xw[NN * HH];
__device__ __align__(16) float g_h2[NN * HH];
__device__ __align__(16) float g_h3[NN * HH];
__device__ __align__(16) float g_deg[NN];
__device__ __align__(16) float g_dinv[NN];
__device__ __align__(16) float g_norm[EE];
__device__ __align__(16) float g_Wp[128 * 512];   // permuted W_hh^T: [k][p]
__device__ __align__(16) float g_wihp[512];       // permuted W_ih
__device__ __align__(16) float g_bp[512];         // permuted b_ih + b_hh

// ---------------- helpers ----------------
__device__ __forceinline__ float sigf(float x) { return 1.0f / (1.0f + __expf(-x)); }

__device__ __forceinline__ void fma2(unsigned long long& d, unsigned long long a, unsigned long long b) {
    asm("fma.rn.f32x2 %0, %1, %2, %0;" : "+l"(d) : "l"(a), "l"(b));
}
__device__ __forceinline__ unsigned long long pack2(float x) {
    unsigned long long r;
    asm("mov.b64 %0, {%1, %1};" : "=l"(r) : "f"(x));
    return r;
}
__device__ __forceinline__ float2 unpack2(unsigned long long v) {
    float2 f;
    asm("mov.b64 {%0, %1}, %2;" : "=f"(f.x), "=f"(f.y) : "l"(v));
    return f;
}

// ---------------- weight permutation ----------------
// gate g in 0..511 (order i,f,g,o blocks of 128), packed index p so that
// thread gate-group gg (0..63) owns p = gg*8 + gt*2 + jj, covering
// hidden indices kh = gg*2 + jj for all four gate types gt.
__global__ void prep_kernel(const float* __restrict__ Whh, const float* __restrict__ Wih,
                            const float* __restrict__ bih, const float* __restrict__ bhh) {
    int g = blockIdx.x * blockDim.x + threadIdx.x;
    if (g >= 512) return;
    int r = g & 127;
    int gt = g >> 7;
    int p = (r >> 1) * 8 + gt * 2 + (r & 1);
    g_wihp[p] = Wih[g];
    g_bp[p] = bih[g] + bhh[g];
    for (int k = 0; k < 128; k++) g_Wp[k * 512 + p] = Whh[g * 128 + k];
}

// ---------------- LSTM (the big kernel) ----------------
// 36 nodes per block, 256 threads: 4 node-groups (9 nodes) x 64 gate-groups (8 gates).
// h kept in smem [k][node]; c in registers; W_hh streamed from L2 in 16 chunks of
// 8 k-rows, single-buffered smem with register prefetch. Packed f32x2 FMA.
__global__ __launch_bounds__(256, 1) void lstm_kernel(const float* __restrict__ x, int N) {
    __shared__ __align__(16) float hs[128][37];       // padded vs bank conflicts
    __shared__ __align__(16) float wcs[8][512];       // 16KB W chunk
    __shared__ __align__(16) float aux[1024];         // wih(512) + b(512)

    int tid = threadIdx.x;
    int ng = tid >> 6;          // 0..3
    int gg = tid & 63;          // 0..63
    int n0 = ng * 9;
    int nbase = blockIdx.x * 36;

    for (int i = tid; i < 512; i += 256) { aux[i] = g_wihp[i]; aux[512 + i] = g_bp[i]; }
    for (int i = tid; i < 128 * 37; i += 256) (&hs[0][0])[i] = 0.f;
    __syncthreads();

    float wihr[8], bbr[8];
#pragma unroll
    for (int j = 0; j < 8; j++) { wihr[j] = aux[gg * 8 + j]; bbr[j] = aux[512 + gg * 8 + j]; }

    float c[9][2];
#pragma unroll
    for (int i = 0; i < 9; i++) { c[i][0] = 0.f; c[i][1] = 0.f; }

    // prefetch W chunk 0 (8 rows x 512 = 1024 float4, 4 per thread)
    float4 pre[4];
#pragma unroll
    for (int p = 0; p < 4; p++) pre[p] = ((const float4*)g_Wp)[tid + p * 256];

    for (int t = 0; t < 128; t++) {
        unsigned long long acc[9][4];
#pragma unroll
        for (int i = 0; i < 9; i++)
#pragma unroll
            for (int j = 0; j < 4; j++) acc[i][j] = 0ull;

        for (int kc = 0; kc < 16; kc++) {
            __syncthreads();   // prev chunk compute done / prev-step hs writes visible
#pragma unroll
            for (int p = 0; p < 4; p++) ((float4*)wcs)[tid + p * 256] = pre[p];
            __syncthreads();
            int nkc = (kc + 1) & 15;
#pragma unroll
            for (int p = 0; p < 4; p++)
                pre[p] = ((const float4*)g_Wp)[nkc * 1024 + tid + p * 256];

#pragma unroll
            for (int k8 = 0; k8 < 8; k8++) {
                int k = kc * 8 + k8;
                ulonglong2 wa = *(ulonglong2*)&wcs[k8][gg * 8];
                ulonglong2 wb = *(ulonglong2*)&wcs[k8][gg * 8 + 4];
#pragma unroll
                for (int i = 0; i < 9; i++) {
                    unsigned long long hh2 = pack2(hs[k][n0 + i]);
                    fma2(acc[i][0], hh2, wa.x);
                    fma2(acc[i][1], hh2, wa.y);
                    fma2(acc[i][2], hh2, wb.x);
                    fma2(acc[i][3], hh2, wb.y);
                }
            }
        }
        __syncthreads();   // all hs reads of this step done before overwriting

        // elementwise LSTM cell update: thread owns 9 nodes x (kh = gg*2, gg*2+1)
#pragma unroll
        for (int i = 0; i < 9; i++) {
            int gn = nbase + n0 + i;
            float xv = (gn < N) ? x[gn * TT + t] : 0.f;
            float2 ai = unpack2(acc[i][0]);
            float2 af = unpack2(acc[i][1]);
            float2 ag = unpack2(acc[i][2]);
            float2 ao = unpack2(acc[i][3]);
            {
                float pi = ai.x + xv * wihr[0] + bbr[0];
                float pf = af.x + xv * wihr[2] + bbr[2];
                float pg = ag.x + xv * wihr[4] + bbr[4];
                float po = ao.x + xv * wihr[6] + bbr[6];
                float cn = sigf(pf) * c[i][0] + sigf(pi) * tanhf(pg);
                c[i][0] = cn;
                hs[gg * 2][n0 + i] = sigf(po) * tanhf(cn);
            }
            {
                float pi = ai.y + xv * wihr[1] + bbr[1];
                float pf = af.y + xv * wihr[3] + bbr[3];
                float pg = ag.y + xv * wihr[5] + bbr[5];
                float po = ao.y + xv * wihr[7] + bbr[7];
                float cn = sigf(pf) * c[i][1] + sigf(pi) * tanhf(pg);
                c[i][1] = cn;
                hs[gg * 2 + 1][n0 + i] = sigf(po) * tanhf(cn);
            }
        }
    }
    __syncthreads();
    // write relu(h_T)
    for (int idx = tid; idx < 36 * 128; idx += 256) {
        int k = idx & 127, n = idx >> 7;
        int gn = nbase + n;
        if (gn < N) g_h1[gn * 128 + k] = fmaxf(hs[k][n], 0.f);
    }
}

// ---------------- GCN dense GEMM: Y[N,128] = X[N,128] @ W[128,128] ----------------
__global__ __launch_bounds__(256) void gemm_k(const float* __restrict__ X,
                                              const float* __restrict__ W,
                                              float* __restrict__ Y, int N) {
    __shared__ __align__(16) float Xs[32][128];   // 16KB
    __shared__ __align__(16) float Ws[64][128];   // 32KB
    int tid = threadIdx.x;
    int node = tid >> 3;        // 0..31
    int jq = tid & 7;
    int j0 = jq * 16;
    int nb = blockIdx.x * 32;

    for (int idx = tid; idx < 32 * 128; idx += 256) {
        int n = idx >> 7, k = idx & 127;
        Xs[n][k] = (nb + n < N) ? X[(nb + n) * 128 + k] : 0.f;
    }
    float4 a0 = make_float4(0.f, 0.f, 0.f, 0.f), a1 = a0, a2 = a0, a3 = a0;

    for (int half = 0; half < 2; half++) {
        __syncthreads();
        for (int idx = tid; idx < 64 * 128; idx += 256) {
            int k = idx >> 7, j = idx & 127;
            Ws[k][j] = W[(half * 64 + k) * 128 + j];
        }
        __syncthreads();
#pragma unroll 8
        for (int k8 = 0; k8 < 64; k8++) {
            float xv = Xs[node][half * 64 + k8];
            const float4* wr = (const float4*)&Ws[k8][j0];
            float4 w0 = wr[0], w1 = wr[1], w2 = wr[2], w3 = wr[3];
            a0.x += xv * w0.x; a0.y += xv * w0.y; a0.z += xv * w0.z; a0.w += xv * w0.w;
            a1.x += xv * w1.x; a1.y += xv * w1.y; a1.z += xv * w1.z; a1.w += xv * w1.w;
            a2.x += xv * w2.x; a2.y += xv * w2.y; a2.z += xv * w2.z; a2.w += xv * w2.w;
            a3.x += xv * w3.x; a3.y += xv * w3.y; a3.z += xv * w3.z; a3.w += xv * w3.w;
        }
    }
    if (nb + node < N) {
        float4* yo = (float4*)&Y[(nb + node) * 128 + j0];
        yo[0] = a0; yo[1] = a1; yo[2] = a2; yo[3] = a3;
    }
}

// ---------------- graph normalization + scatter ----------------
__global__ void deg_init(int N) {
    int i = blockIdx.x * blockDim.x + threadIdx.x;
    if (i < N) g_deg[i] = 1.0f;   // self-loop weight
}
__global__ void deg_scatter(const int* __restrict__ col, const float* __restrict__ ew, int E) {
    int e = blockIdx.x * blockDim.x + threadIdx.x;
    if (e < E) atomicAdd(&g_deg[col[e]], ew[e]);
}
__global__ void dinv_k(int N) {
    int i = blockIdx.x * blockDim.x + threadIdx.x;
    if (i < N) g_dinv[i] = rsqrtf(g_deg[i]);
}
__global__ void norm_k(const int* __restrict__ row, const int* __restrict__ col,
                       const float* __restrict__ ew, int E) {
    int e = blockIdx.x * blockDim.x + threadIdx.x;
    if (e < E) g_norm[e] = g_dinv[row[e]] * ew[e] * g_dinv[col[e]];
}
// dst[n] = dinv[n]^2 * src[n]   (self-loop term), float4 per thread
__global__ void self_init(const float* __restrict__ src, float* __restrict__ dst, int N) {
    int gid = blockIdx.x * blockDim.x + threadIdx.x;
    if (gid >= N * 32) return;
    int n = gid >> 5;
    float d = g_dinv[n];
    float s = d * d;
    float4 v = ((const float4*)src)[gid];
    v.x *= s; v.y *= s; v.z *= s; v.w *= s;
    ((float4*)dst)[gid] = v;
}
// warp per edge: dst[col] += norm[e] * src[row]
__global__ void scatter_k(const float* __restrict__ src, float* __restrict__ dst,
                          const int* __restrict__ row, const int* __restrict__ col, int E) {
    int gid = blockIdx.x * blockDim.x + threadIdx.x;
    int e = gid >> 5;
    if (e >= E) return;
    int lane = gid & 31;
    int r = row[e], cc = col[e];
    float nv = g_norm[e];
    float4 v = ((const float4*)(src + r * 128))[lane];
    float* d = dst + cc * 128 + lane * 4;
    atomicAdd(d + 0, nv * v.x);
    atomicAdd(d + 1, nv * v.y);
    atomicAdd(d + 2, nv * v.z);
    atomicAdd(d + 3, nv * v.w);
}
__global__ void bias_relu(float* __restrict__ h, const float* __restrict__ b, int N) {
    int gid = blockIdx.x * blockDim.x + threadIdx.x;
    if (gid < N * 128) h[gid] = fmaxf(h[gid] + b[gid & 127], 0.f);
}
// mean over nodes + b2: one block per feature
__global__ void pool_k(const float* __restrict__ h, const float* __restrict__ b2,
                       float* __restrict__ out, int N) {
    int f = blockIdx.x;
    float s = 0.f;
    for (int n = threadIdx.x; n < N; n += blockDim.x) s += h[n * 128 + f];
    __shared__ float red[256];
    red[threadIdx.x] = s;
    __syncthreads();
    for (int o = 128; o > 0; o >>= 1) {
        if (threadIdx.x < o) red[threadIdx.x] += red[threadIdx.x + o];
        __syncthreads();
    }
    if (threadIdx.x == 0) out[f] = red[0] / (float)N + b2[f];
}

// ---------------- launch ----------------
extern "C" void kernel_launch(void* const* d_in, const int* in_sizes, int n_in,
                              void* d_out, int out_size) {
    const float* x   = (const float*)d_in[0];
    const int*   ei  = (const int*)d_in[1];
    const float* ew  = (const float*)d_in[2];
    const float* Wih = (const float*)d_in[3];
    const float* Whh = (const float*)d_in[4];
    const float* bih = (const float*)d_in[5];
    const float* bhh = (const float*)d_in[6];
    const float* W1  = (const float*)d_in[7];
    const float* b1  = (const float*)d_in[8];
    const float* W2  = (const float*)d_in[9];
    const float* b2  = (const float*)d_in[10];
    float* out = (float*)d_out;

    int N = in_sizes[0] / TT;
    int E = in_sizes[2];
    const int* row = ei;
    const int* col = ei + E;

    float *p_h1, *p_xw, *p_h2, *p_h3;
    cudaGetSymbolAddress((void**)&p_h1, g_h1);
    cudaGetSymbolAddress((void**)&p_xw, g_xw);
    cudaGetSymbolAddress((void**)&p_h2, g_h2);
    cudaGetSymbolAddress((void**)&p_h3, g_h3);

    int nb256 = (N + 255) / 256;
    int eb256 = (E + 255) / 256;

    prep_kernel<<<2, 256>>>(Whh, Wih, bih, bhh);
    lstm_kernel<<<(N + 35) / 36, 256>>>(x, N);                 // -> g_h1 (relu'd)

    deg_init<<<nb256, 256>>>(N);
    deg_scatter<<<eb256, 256>>>(col, ew, E);
    dinv_k<<<nb256, 256>>>(N);
    norm_k<<<eb256, 256>>>(row, col, ew, E);

    // GCN layer 1
    gemm_k<<<(N + 31) / 32, 256>>>(p_h1, W1, p_xw, N);
    self_init<<<(N * 32 + 255) / 256, 256>>>(p_xw, p_h2, N);
    scatter_k<<<(E * 32 + 255) / 256, 256>>>(p_xw, p_h2, row, col, E);
    bias_relu<<<(N * 128 + 255) / 256, 256>>>(p_h2, b1, N);

    // GCN layer 2
    gemm_k<<<(N + 31) / 32, 256>>>(p_h2, W2, p_xw, N);
    self_init<<<(N * 32 + 255) / 256, 256>>>(p_xw, p_h3, N);
    scatter_k<<<(E * 32 + 255) / 256, 256>>>(p_xw, p_h3, row, col, E);

    pool_k<<<128, 256>>>(p_h3, b2, out, N);
}

// round 2
// speedup vs baseline: 1.0015x; 1.0015x over previous
#include <cuda_runtime.h>
#include <math.h>

#define NN 10000
#define TT 128
#define HH 128
#define EE 320000

// ---------------- device scratch (no allocations allowed) ----------------
__device__ __align__(16) float g_h1[NN * HH];
__device__ __align__(16) float g_xw[NN * HH];
__device__ __align__(16) float g_h2[NN * HH];
__device__ __align__(16) float g_h3[NN * HH];
__device__ __align__(16) float g_deg[NN];
__device__ __align__(16) float g_dinv[NN];
__device__ __align__(16) float g_norm[EE];
__device__ __align__(16) float g_Wp[128 * 512];   // permuted W_hh^T: [k][p]
__device__ __align__(16) float g_wihp[512];       // permuted W_ih
__device__ __align__(16) float g_bp[512];         // permuted b_ih + b_hh

// ---------------- helpers ----------------
__device__ __forceinline__ float sigf(float x) { return 1.0f / (1.0f + __expf(-x)); }

__device__ __forceinline__ void fma2(unsigned long long& d, unsigned long long a, unsigned long long b) {
    asm("fma.rn.f32x2 %0, %1, %2, %0;" : "+l"(d) : "l"(a), "l"(b));
}
__device__ __forceinline__ unsigned long long pack2(float x) {
    unsigned long long r;
    asm("mov.b64 %0, {%1, %1};" : "=l"(r) : "f"(x));
    return r;
}
__device__ __forceinline__ float2 unpack2(unsigned long long v) {
    float2 f;
    asm("mov.b64 {%0, %1}, %2;" : "=f"(f.x), "=f"(f.y) : "l"(v));
    return f;
}

// ---------------- weight permutation ----------------
// gate g in 0..511 (order i,f,g,o blocks of 128), packed index p so that
// thread gate-group gg (0..63) owns p = gg*8 + gt*2 + jj, covering
// hidden indices kh = gg*2 + jj for all four gate types gt.
__global__ void prep_kernel(const float* __restrict__ Whh, const float* __restrict__ Wih,
                            const float* __restrict__ bih, const float* __restrict__ bhh) {
    int g = blockIdx.x * blockDim.x + threadIdx.x;
    if (g >= 512) return;
    int r = g & 127;
    int gt = g >> 7;
    int p = (r >> 1) * 8 + gt * 2 + (r & 1);
    g_wihp[p] = Wih[g];
    g_bp[p] = bih[g] + bhh[g];
    for (int k = 0; k < 128; k++) g_Wp[k * 512 + p] = Whh[g * 128 + k];
}

// ---------------- LSTM (the big kernel) ----------------
// 36 nodes per block, 256 threads: 4 node-groups (9 nodes) x 64 gate-groups (8 gates).
// h kept in smem [k][node]; c in registers; W_hh streamed from L2 in 16 chunks of
// 8 k-rows, single-buffered smem with register prefetch. Packed f32x2 FMA.
__global__ __launch_bounds__(256, 1) void lstm_kernel(const float* __restrict__ x, int N) {
    __shared__ __align__(16) float hs[128][37];       // padded vs bank conflicts
    __shared__ __align__(16) float wcs[8][512];       // 16KB W chunk
    __shared__ __align__(16) float aux[1024];         // wih(512) + b(512)

    int tid = threadIdx.x;
    int ng = tid >> 6;          // 0..3
    int gg = tid & 63;          // 0..63
    int n0 = ng * 9;
    int nbase = blockIdx.x * 36;

    for (int i = tid; i < 512; i += 256) { aux[i] = g_wihp[i]; aux[512 + i] = g_bp[i]; }
    for (int i = tid; i < 128 * 37; i += 256) (&hs[0][0])[i] = 0.f;
    __syncthreads();

    float wihr[8], bbr[8];
#pragma unroll
    for (int j = 0; j < 8; j++) { wihr[j] = aux[gg * 8 + j]; bbr[j] = aux[512 + gg * 8 + j]; }

    float c[9][2];
#pragma unroll
    for (int i = 0; i < 9; i++) { c[i][0] = 0.f; c[i][1] = 0.f; }

    // prefetch W chunk 0 (8 rows x 512 = 1024 float4, 4 per thread)
    float4 pre[4];
#pragma unroll
    for (int p = 0; p < 4; p++) pre[p] = ((const float4*)g_Wp)[tid + p * 256];

    for (int t = 0; t < 128; t++) {
        unsigned long long acc[9][4];
#pragma unroll
        for (int i = 0; i < 9; i++)
#pragma unroll
            for (int j = 0; j < 4; j++) acc[i][j] = 0ull;

        for (int kc = 0; kc < 16; kc++) {
            __syncthreads();   // prev chunk compute done / prev-step hs writes visible
#pragma unroll
            for (int p = 0; p < 4; p++) ((float4*)wcs)[tid + p * 256] = pre[p];
            __syncthreads();
            int nkc = (kc + 1) & 15;
#pragma unroll
            for (int p = 0; p < 4; p++)
                pre[p] = ((const float4*)g_Wp)[nkc * 1024 + tid + p * 256];

#pragma unroll
            for (int k8 = 0; k8 < 8; k8++) {
                int k = kc * 8 + k8;
                ulonglong2 wa = *(ulonglong2*)&wcs[k8][gg * 8];
                ulonglong2 wb = *(ulonglong2*)&wcs[k8][gg * 8 + 4];
#pragma unroll
                for (int i = 0; i < 9; i++) {
                    unsigned long long hh2 = pack2(hs[k][n0 + i]);
                    fma2(acc[i][0], hh2, wa.x);
                    fma2(acc[i][1], hh2, wa.y);
                    fma2(acc[i][2], hh2, wb.x);
                    fma2(acc[i][3], hh2, wb.y);
                }
            }
        }
        __syncthreads();   // all hs reads of this step done before overwriting

        // elementwise LSTM cell update: thread owns 9 nodes x (kh = gg*2, gg*2+1)
#pragma unroll
        for (int i = 0; i < 9; i++) {
            int gn = nbase + n0 + i;
            float xv = (gn < N) ? x[gn * TT + t] : 0.f;
            float2 ai = unpack2(acc[i][0]);
            float2 af = unpack2(acc[i][1]);
            float2 ag = unpack2(acc[i][2]);
            float2 ao = unpack2(acc[i][3]);
            {
                float pi = ai.x + xv * wihr[0] + bbr[0];
                float pf = af.x + xv * wihr[2] + bbr[2];
                float pg = ag.x + xv * wihr[4] + bbr[4];
                float po = ao.x + xv * wihr[6] + bbr[6];
                float cn = sigf(pf) * c[i][0] + sigf(pi) * tanhf(pg);
                c[i][0] = cn;
                hs[gg * 2][n0 + i] = sigf(po) * tanhf(cn);
            }
            {
                float pi = ai.y + xv * wihr[1] + bbr[1];
                float pf = af.y + xv * wihr[3] + bbr[3];
                float pg = ag.y + xv * wihr[5] + bbr[5];
                float po = ao.y + xv * wihr[7] + bbr[7];
                float cn = sigf(pf) * c[i][1] + sigf(pi) * tanhf(pg);
                c[i][1] = cn;
                hs[gg * 2 + 1][n0 + i] = sigf(po) * tanhf(cn);
            }
        }
    }
    __syncthreads();
    // write relu(h_T)
    for (int idx = tid; idx < 36 * 128; idx += 256) {
        int k = idx & 127, n = idx >> 7;
        int gn = nbase + n;
        if (gn < N) g_h1[gn * 128 + k] = fmaxf(hs[k][n], 0.f);
    }
}

// ---------------- GCN dense GEMM: Y[N,128] = X[N,128] @ W[128,128] ----------------
__global__ __launch_bounds__(256) void gemm_k(const float* __restrict__ X,
                                              const float* __restrict__ W,
                                              float* __restrict__ Y, int N) {
    __shared__ __align__(16) float Xs[32][128];   // 16KB
    __shared__ __align__(16) float Ws[64][128];   // 32KB
    int tid = threadIdx.x;
    int node = tid >> 3;        // 0..31
    int jq = tid & 7;
    int j0 = jq * 16;
    int nb = blockIdx.x * 32;

    for (int idx = tid; idx < 32 * 128; idx += 256) {
        int n = idx >> 7, k = idx & 127;
        Xs[n][k] = (nb + n < N) ? X[(nb + n) * 128 + k] : 0.f;
    }
    float4 a0 = make_float4(0.f, 0.f, 0.f, 0.f), a1 = a0, a2 = a0, a3 = a0;

    for (int half = 0; half < 2; half++) {
        __syncthreads();
        for (int idx = tid; idx < 64 * 128; idx += 256) {
            int k = idx >> 7, j = idx & 127;
            Ws[k][j] = W[(half * 64 + k) * 128 + j];
        }
        __syncthreads();
#pragma unroll 8
        for (int k8 = 0; k8 < 64; k8++) {
            float xv = Xs[node][half * 64 + k8];
            const float4* wr = (const float4*)&Ws[k8][j0];
            float4 w0 = wr[0], w1 = wr[1], w2 = wr[2], w3 = wr[3];
            a0.x += xv * w0.x; a0.y += xv * w0.y; a0.z += xv * w0.z; a0.w += xv * w0.w;
            a1.x += xv * w1.x; a1.y += xv * w1.y; a1.z += xv * w1.z; a1.w += xv * w1.w;
            a2.x += xv * w2.x; a2.y += xv * w2.y; a2.z += xv * w2.z; a2.w += xv * w2.w;
            a3.x += xv * w3.x; a3.y += xv * w3.y; a3.z += xv * w3.z; a3.w += xv * w3.w;
        }
    }
    if (nb + node < N) {
        float4* yo = (float4*)&Y[(nb + node) * 128 + j0];
        yo[0] = a0; yo[1] = a1; yo[2] = a2; yo[3] = a3;
    }
}

// ---------------- graph normalization + scatter ----------------
__global__ void deg_init(int N) {
    int i = blockIdx.x * blockDim.x + threadIdx.x;
    if (i < N) g_deg[i] = 1.0f;   // self-loop weight
}
__global__ void deg_scatter(const int* __restrict__ col, const float* __restrict__ ew, int E) {
    int e = blockIdx.x * blockDim.x + threadIdx.x;
    if (e < E) atomicAdd(&g_deg[col[e]], ew[e]);
}
__global__ void dinv_k(int N) {
    int i = blockIdx.x * blockDim.x + threadIdx.x;
    if (i < N) g_dinv[i] = rsqrtf(g_deg[i]);
}
__global__ void norm_k(const int* __restrict__ row, const int* __restrict__ col,
                       const float* __restrict__ ew, int E) {
    int e = blockIdx.x * blockDim.x + threadIdx.x;
    if (e < E) g_norm[e] = g_dinv[row[e]] * ew[e] * g_dinv[col[e]];
}
// dst[n] = dinv[n]^2 * src[n]   (self-loop term), float4 per thread
__global__ void self_init(const float* __restrict__ src, float* __restrict__ dst, int N) {
    int gid = blockIdx.x * blockDim.x + threadIdx.x;
    if (gid >= N * 32) return;
    int n = gid >> 5;
    float d = g_dinv[n];
    float s = d * d;
    float4 v = ((const float4*)src)[gid];
    v.x *= s; v.y *= s; v.z *= s; v.w *= s;
    ((float4*)dst)[gid] = v;
}
// warp per edge: dst[col] += norm[e] * src[row]
__global__ void scatter_k(const float* __restrict__ src, float* __restrict__ dst,
                          const int* __restrict__ row, const int* __restrict__ col, int E) {
    int gid = blockIdx.x * blockDim.x + threadIdx.x;
    int e = gid >> 5;
    if (e >= E) return;
    int lane = gid & 31;
    int r = row[e], cc = col[e];
    float nv = g_norm[e];
    float4 v = ((const float4*)(src + r * 128))[lane];
    float* d = dst + cc * 128 + lane * 4;
    atomicAdd(d + 0, nv * v.x);
    atomicAdd(d + 1, nv * v.y);
    atomicAdd(d + 2, nv * v.z);
    atomicAdd(d + 3, nv * v.w);
}
__global__ void bias_relu(float* __restrict__ h, const float* __restrict__ b, int N) {
    int gid = blockIdx.x * blockDim.x + threadIdx.x;
    if (gid < N * 128) h[gid] = fmaxf(h[gid] + b[gid & 127], 0.f);
}
// mean over nodes + b2: one block per feature
__global__ void pool_k(const float* __restrict__ h, const float* __restrict__ b2,
                       float* __restrict__ out, int N) {
    int f = blockIdx.x;
    float s = 0.f;
    for (int n = threadIdx.x; n < N; n += blockDim.x) s += h[n * 128 + f];
    __shared__ float red[256];
    red[threadIdx.x] = s;
    __syncthreads();
    for (int o = 128; o > 0; o >>= 1) {
        if (threadIdx.x < o) red[threadIdx.x] += red[threadIdx.x + o];
        __syncthreads();
    }
    if (threadIdx.x == 0) out[f] = red[0] / (float)N + b2[f];
}

// ---------------- launch ----------------
extern "C" void kernel_launch(void* const* d_in, const int* in_sizes, int n_in,
                              void* d_out, int out_size) {
    const float* x   = (const float*)d_in[0];
    const int*   ei  = (const int*)d_in[1];
    const float* ew  = (const float*)d_in[2];
    const float* Wih = (const float*)d_in[3];
    const float* Whh = (const float*)d_in[4];
    const float* bih = (const float*)d_in[5];
    const float* bhh = (const float*)d_in[6];
    const float* W1  = (const float*)d_in[7];
    const float* b1  = (const float*)d_in[8];
    const float* W2  = (const float*)d_in[9];
    const float* b2  = (const float*)d_in[10];
    float* out = (float*)d_out;

    int N = in_sizes[0] / TT;
    int E = in_sizes[2];
    const int* row = ei;
    const int* col = ei + E;

    float *p_h1, *p_xw, *p_h2, *p_h3;
    cudaGetSymbolAddress((void**)&p_h1, g_h1);
    cudaGetSymbolAddress((void**)&p_xw, g_xw);
    cudaGetSymbolAddress((void**)&p_h2, g_h2);
    cudaGetSymbolAddress((void**)&p_h3, g_h3);

    int nb256 = (N + 255) / 256;
    int eb256 = (E + 255) / 256;

    prep_kernel<<<2, 256>>>(Whh, Wih, bih, bhh);
    lstm_kernel<<<(N + 35) / 36, 256>>>(x, N);                 // -> g_h1 (relu'd)

    deg_init<<<nb256, 256>>>(N);
    deg_scatter<<<eb256, 256>>>(col, ew, E);
    dinv_k<<<nb256, 256>>>(N);
    norm_k<<<eb256, 256>>>(row, col, ew, E);

    // GCN layer 1
    gemm_k<<<(N + 31) / 32, 256>>>(p_h1, W1, p_xw, N);
    self_init<<<(N * 32 + 255) / 256, 256>>>(p_xw, p_h2, N);
    scatter_k<<<(E * 32 + 255) / 256, 256>>>(p_xw, p_h2, row, col, E);
    bias_relu<<<(N * 128 + 255) / 256, 256>>>(p_h2, b1, N);

    // GCN layer 2
    gemm_k<<<(N + 31) / 32, 256>>>(p_h2, W2, p_xw, N);
    self_init<<<(N * 32 + 255) / 256, 256>>>(p_xw, p_h3, N);
    scatter_k<<<(E * 32 + 255) / 256, 256>>>(p_xw, p_h3, row, col, E);

    pool_k<<<128, 256>>>(p_h3, b2, out, N);
}